// round 13
// baseline (speedup 1.0000x reference)
#include <cuda_runtime.h>
#include <math.h>

#define N_NODES 50000
#define N_EDGES 1600000
#define NFEAT 256
#define NHID 64
#define NCLASS 16

// ---------------------------------------------------------------------------
// Static scratch — no cudaMalloc allowed anywhere.
// ---------------------------------------------------------------------------
__device__ float g_sup1[N_NODES * NHID];    // x @ W1
__device__ float g_sup2[N_NODES * NCLASS];  // relu(spmm1+b1) @ W2 (fused)
__device__ int   g_deg[N_NODES];            // per-dst edge counts
__device__ int   g_rowptr[N_NODES];         // CSR row starts
__device__ int   g_rank[N_EDGES];           // per-edge rank within its dst row
__device__ int2  g_edge[N_EDGES];           // packed {src, bits(weight)} CSR order

// ---------------------------------------------------------------------------
// 0) zero the histogram
// ---------------------------------------------------------------------------
__global__ void zero_deg_kernel() {
    int i = blockIdx.x * blockDim.x + threadIdx.x;
    if (i < N_NODES) g_deg[i] = 0;
}

// ---------------------------------------------------------------------------
// 1) histogram of dst — 8 edges/thread; ALSO record each edge's rank
//    (the atomic's return value) so the scatter pass needs no atomics.
// ---------------------------------------------------------------------------
__global__ void hist_kernel(const int* __restrict__ dst) {
    const int NT = N_EDGES / 8;
    int t = blockIdx.x * blockDim.x + threadIdx.x;
    if (t >= NT) return;
    int d[8];
#pragma unroll
    for (int j = 0; j < 8; j++) d[j] = __ldg(&dst[t + j * NT]);
    int r[8];
#pragma unroll
    for (int j = 0; j < 8; j++) r[j] = atomicAdd(&g_deg[d[j]], 1);
#pragma unroll
    for (int j = 0; j < 8; j++) g_rank[t + j * NT] = r[j];
}

// ---------------------------------------------------------------------------
// 2) exclusive scan over g_deg -> g_rowptr (1 block, shfl warp scan)
// ---------------------------------------------------------------------------
__global__ void __launch_bounds__(1024)
scan_kernel() {
    __shared__ int warpsum[32];
    __shared__ int warpoff[32];
    __shared__ int carry_s;
    int tid  = threadIdx.x;
    int lane = tid & 31;
    int wrp  = tid >> 5;
    if (tid == 0) carry_s = 0;
    __syncthreads();

    for (int base = 0; base < N_NODES; base += 1024) {
        int i = base + tid;
        int v = (i < N_NODES) ? g_deg[i] : 0;

        int incl = v;
#pragma unroll
        for (int off = 1; off < 32; off <<= 1) {
            int t = __shfl_up_sync(0xffffffffu, incl, off);
            if (lane >= off) incl += t;
        }
        if (lane == 31) warpsum[wrp] = incl;
        __syncthreads();

        if (wrp == 0) {
            int s = warpsum[lane];
            int si = s;
#pragma unroll
            for (int off = 1; off < 32; off <<= 1) {
                int t = __shfl_up_sync(0xffffffffu, si, off);
                if (lane >= off) si += t;
            }
            warpoff[lane] = si - s;
        }
        __syncthreads();

        if (i < N_NODES) g_rowptr[i] = carry_s + warpoff[wrp] + incl - v;
        __syncthreads();
        if (tid == 0) carry_s += warpoff[31] + warpsum[31];
        __syncthreads();
    }
}

// ---------------------------------------------------------------------------
// 3) scatter edges into CSR order — NO atomics: p = rowptr[dst] + rank.
//    8 edges/thread; rowptr (200KB) is L1/L2 resident.
// ---------------------------------------------------------------------------
__global__ void scatter_kernel(const int* __restrict__ src,
                               const int* __restrict__ dst,
                               const float* __restrict__ w) {
    const int NT = N_EDGES / 8;
    int t = blockIdx.x * blockDim.x + threadIdx.x;
    if (t >= NT) return;

    int d[8], s[8], r[8];
    float wt[8];
#pragma unroll
    for (int j = 0; j < 8; j++) d[j] = __ldg(&dst[t + j * NT]);
#pragma unroll
    for (int j = 0; j < 8; j++) s[j] = __ldg(&src[t + j * NT]);
#pragma unroll
    for (int j = 0; j < 8; j++) r[j] = __ldg(&g_rank[t + j * NT]);
#pragma unroll
    for (int j = 0; j < 8; j++) wt[j] = __ldg(&w[t + j * NT]);

    int p[8];
#pragma unroll
    for (int j = 0; j < 8; j++) p[j] = __ldg(&g_rowptr[d[j]]) + r[j];
#pragma unroll
    for (int j = 0; j < 8; j++)
        g_edge[p[j]] = make_int2(s[j], __float_as_int(wt[j]));
}

// ---------------------------------------------------------------------------
// GEMM1: sup1[50000,64] = x[50000,256] @ W1[256,64]
// 64x64 tile, 256 threads, 4x4 register blocking, BK=16, reg prefetch.
// ---------------------------------------------------------------------------
__global__ void __launch_bounds__(256)
gemm1_kernel(const float* __restrict__ x, const float* __restrict__ W1) {
    __shared__ float xs[16][68];
    __shared__ float ws[16][64];

    int tid = threadIdx.x;
    int tx = tid & 15;
    int ty = tid >> 4;
    int rowBase = blockIdx.x * 64;

    int xr  = tid >> 2;
    int xkq = (tid & 3) * 4;
    int wkk = tid >> 4;
    int wn  = (tid & 15) * 4;
    int grow = rowBase + xr;
    bool rowOK = (grow < N_NODES);

    float acc[4][4];
#pragma unroll
    for (int i = 0; i < 4; i++)
#pragma unroll
        for (int j = 0; j < 4; j++) acc[i][j] = 0.f;

    float4 xv = rowOK ? *(const float4*)(x + (size_t)grow * NFEAT + 0 + xkq)
                      : make_float4(0.f, 0.f, 0.f, 0.f);
    float4 wv = *(const float4*)(W1 + (size_t)(0 + wkk) * NHID + wn);

    for (int k0 = 0; k0 < NFEAT; k0 += 16) {
        xs[xkq + 0][xr] = xv.x;
        xs[xkq + 1][xr] = xv.y;
        xs[xkq + 2][xr] = xv.z;
        xs[xkq + 3][xr] = xv.w;
        *(float4*)&ws[wkk][wn] = wv;
        __syncthreads();

        int k1 = k0 + 16;
        if (k1 < NFEAT) {
            xv = rowOK ? *(const float4*)(x + (size_t)grow * NFEAT + k1 + xkq)
                       : make_float4(0.f, 0.f, 0.f, 0.f);
            wv = *(const float4*)(W1 + (size_t)(k1 + wkk) * NHID + wn);
        }

#pragma unroll
        for (int kk = 0; kk < 16; kk++) {
            float a0 = xs[kk][ty * 4 + 0];
            float a1 = xs[kk][ty * 4 + 1];
            float a2 = xs[kk][ty * 4 + 2];
            float a3 = xs[kk][ty * 4 + 3];
            float4 bv = *(float4*)&ws[kk][tx * 4];
            acc[0][0] += a0 * bv.x; acc[0][1] += a0 * bv.y; acc[0][2] += a0 * bv.z; acc[0][3] += a0 * bv.w;
            acc[1][0] += a1 * bv.x; acc[1][1] += a1 * bv.y; acc[1][2] += a1 * bv.z; acc[1][3] += a1 * bv.w;
            acc[2][0] += a2 * bv.x; acc[2][1] += a2 * bv.y; acc[2][2] += a2 * bv.z; acc[2][3] += a2 * bv.w;
            acc[3][0] += a3 * bv.x; acc[3][1] += a3 * bv.y; acc[3][2] += a3 * bv.z; acc[3][3] += a3 * bv.w;
        }
        __syncthreads();
    }

#pragma unroll
    for (int i = 0; i < 4; i++) {
        int gr = rowBase + ty * 4 + i;
        if (gr < N_NODES) {
            float4 v = make_float4(acc[i][0], acc[i][1], acc[i][2], acc[i][3]);
            *(float4*)(g_sup1 + (size_t)gr * NHID + tx * 4) = v;
        }
    }
}

// ---------------------------------------------------------------------------
// 4) FUSED SpMM1 + bias + ReLU + GEMM2:
//    sup2[row] = relu(b1 + sum_e w_e * sup1[src_e]) @ W2
//    16 threads/row, each owns 4 features. 8-way unrolled gather, then
//    per-lane 4x16 partial GEMM + width-16 shfl butterfly reduction.
//    Grid is exact: 50000*16/256 = 3125 blocks, no bounds checks needed.
// ---------------------------------------------------------------------------
__global__ void __launch_bounds__(256)
spmm1_fused_kernel(const float* __restrict__ b1, const float* __restrict__ W2) {
    __shared__ float w2t[NCLASS * NHID + 16];  // transposed [c][k], padded
    for (int i = threadIdx.x; i < NCLASS * NHID; i += 256) {
        int c = i >> 6;         // 0..15
        int k = i & 63;         // 0..63
        w2t[c * NHID + k] = W2[k * NCLASS + c];
    }
    __syncthreads();

    long long t = (long long)blockIdx.x * blockDim.x + threadIdx.x;
    int row = (int)(t >> 4);
    int sub = (int)(t & 15);

    int start = g_rowptr[row];
    int end   = start + g_deg[row];

    float4 acc = make_float4(0.f, 0.f, 0.f, 0.f);
    int e = start;
    for (; e + 8 <= end; e += 8) {
        int2 p[8];
#pragma unroll
        for (int u = 0; u < 8; u++) p[u] = __ldg(&g_edge[e + u]);
        float4 v[8];
#pragma unroll
        for (int u = 0; u < 8; u++)
            v[u] = *(const float4*)(g_sup1 + (size_t)p[u].x * NHID + sub * 4);
#pragma unroll
        for (int u = 0; u < 8; u++) {
            float wt = __int_as_float(p[u].y);
            acc.x += wt * v[u].x; acc.y += wt * v[u].y;
            acc.z += wt * v[u].z; acc.w += wt * v[u].w;
        }
    }
    for (; e < end; e++) {
        int2 p = __ldg(&g_edge[e]);
        float wt = __int_as_float(p.y);
        float4 v = *(const float4*)(g_sup1 + (size_t)p.x * NHID + sub * 4);
        acc.x += wt * v.x; acc.y += wt * v.y; acc.z += wt * v.z; acc.w += wt * v.w;
    }

    // bias + ReLU
    float4 bv = *(const float4*)(b1 + sub * 4);
    acc.x = fmaxf(acc.x + bv.x, 0.f);
    acc.y = fmaxf(acc.y + bv.y, 0.f);
    acc.z = fmaxf(acc.z + bv.z, 0.f);
    acc.w = fmaxf(acc.w + bv.w, 0.f);

    // per-lane partial GEMM: p[c] over this lane's 4 k's
    float p[NCLASS];
#pragma unroll
    for (int c = 0; c < NCLASS; c++) {
        float4 wv = *(const float4*)&w2t[c * NHID + sub * 4];
        p[c] = acc.x * wv.x + acc.y * wv.y + acc.z * wv.z + acc.w * wv.w;
    }
    // butterfly sum across the 16-lane row group
#pragma unroll
    for (int off = 8; off > 0; off >>= 1)
#pragma unroll
        for (int c = 0; c < NCLASS; c++)
            p[c] += __shfl_xor_sync(0xffffffffu, p[c], off, 16);

    // lanes 0..3 write 4 classes each (static selection, no dynamic indexing)
    if (sub < 4) {
        float4 o;
        if      (sub == 0) o = make_float4(p[0],  p[1],  p[2],  p[3]);
        else if (sub == 1) o = make_float4(p[4],  p[5],  p[6],  p[7]);
        else if (sub == 2) o = make_float4(p[8],  p[9],  p[10], p[11]);
        else               o = make_float4(p[12], p[13], p[14], p[15]);
        *(float4*)(g_sup2 + (size_t)row * NCLASS + sub * 4) = o;
    }
}

// ---------------------------------------------------------------------------
// 5) SpMM2 gather + bias + log_softmax, fused. 4 threads/row, 8-way unroll.
// ---------------------------------------------------------------------------
__global__ void __launch_bounds__(256)
spmm2_csr_kernel(const float* __restrict__ b2, float* __restrict__ out) {
    long long t = (long long)blockIdx.x * blockDim.x + threadIdx.x;
    int row = (int)(t >> 2);
    int sub = (int)(t & 3);
    if (row >= N_NODES) return;

    int start = g_rowptr[row];
    int end   = start + g_deg[row];

    float4 acc = make_float4(0.f, 0.f, 0.f, 0.f);
    int e = start;
    for (; e + 8 <= end; e += 8) {
        int2 p[8];
#pragma unroll
        for (int u = 0; u < 8; u++) p[u] = __ldg(&g_edge[e + u]);
        float4 v[8];
#pragma unroll
        for (int u = 0; u < 8; u++)
            v[u] = *(const float4*)(g_sup2 + (size_t)p[u].x * NCLASS + sub * 4);
#pragma unroll
        for (int u = 0; u < 8; u++) {
            float wt = __int_as_float(p[u].y);
            acc.x += wt * v[u].x; acc.y += wt * v[u].y;
            acc.z += wt * v[u].z; acc.w += wt * v[u].w;
        }
    }
    for (; e < end; e++) {
        int2 p = __ldg(&g_edge[e]);
        float wt = __int_as_float(p.y);
        float4 v = *(const float4*)(g_sup2 + (size_t)p.x * NCLASS + sub * 4);
        acc.x += wt * v.x; acc.y += wt * v.y; acc.z += wt * v.z; acc.w += wt * v.w;
    }
    float4 bv = *(const float4*)(b2 + sub * 4);
    acc.x += bv.x; acc.y += bv.y; acc.z += bv.z; acc.w += bv.w;

    // log_softmax across the 4-lane group (16 classes total)
    float m = fmaxf(fmaxf(acc.x, acc.y), fmaxf(acc.z, acc.w));
    m = fmaxf(m, __shfl_xor_sync(0xffffffffu, m, 1, 4));
    m = fmaxf(m, __shfl_xor_sync(0xffffffffu, m, 2, 4));

    float s = expf(acc.x - m) + expf(acc.y - m) +
              expf(acc.z - m) + expf(acc.w - m);
    s += __shfl_xor_sync(0xffffffffu, s, 1, 4);
    s += __shfl_xor_sync(0xffffffffu, s, 2, 4);

    float lse = m + logf(s);
    acc.x -= lse; acc.y -= lse; acc.z -= lse; acc.w -= lse;
    *(float4*)(out + (size_t)row * NCLASS + sub * 4) = acc;
}

// ---------------------------------------------------------------------------
// Launch sequence (graph-capturable, default stream, no allocations)
// ---------------------------------------------------------------------------
extern "C" void kernel_launch(void* const* d_in, const int* in_sizes, int n_in,
                              void* d_out, int out_size) {
    const float* x        = (const float*)d_in[0];
    const float* W1       = (const float*)d_in[1];
    const float* b1       = (const float*)d_in[2];
    const float* W2       = (const float*)d_in[3];
    const float* b2       = (const float*)d_in[4];
    const int*   edge_src = (const int*)d_in[5];
    const int*   edge_dst = (const int*)d_in[6];
    const float* edge_w   = (const float*)d_in[7];
    float* out = (float*)d_out;

    // CSR build (single atomic pass; scatter is atomic-free)
    zero_deg_kernel<<<(N_NODES + 255) / 256, 256>>>();
    hist_kernel<<<(N_EDGES / 8 + 255) / 256, 256>>>(edge_dst);
    scan_kernel<<<1, 1024>>>();
    scatter_kernel<<<(N_EDGES / 8 + 255) / 256, 256>>>(edge_src, edge_dst, edge_w);

    // Dense pipeline (gemm2 fused into spmm1 epilogue)
    gemm1_kernel<<<(N_NODES + 63) / 64, 256>>>(x, W1);
    spmm1_fused_kernel<<<(N_NODES * 16) / 256, 256>>>(b1, W2);
    {
        long long threads = (long long)N_NODES * 4;
        spmm2_csr_kernel<<<(int)((threads + 255) / 256), 256>>>(b2, out);
    }
}